// round 4
// baseline (speedup 1.0000x reference)
#include <cuda_runtime.h>
#include <cuda_bf16.h>

#define BB 16384
#define SS 4
#define LL 16
#define DD 256
#define BOS_ID 98
#define D4 (DD / 4)   // 64 float4 per row

__device__ __forceinline__ int comp(const int4 v, int i) {
    switch (i) { case 0: return v.x; case 1: return v.y; case 2: return v.z; default: return v.w; }
}

// One warp per batch element b. Produces 5 output rows (BOS + 4 slots).
// Each lane owns columns lane and lane+32 of every row.
__global__ void __launch_bounds__(256) actions_emb_kernel(
    const int*    __restrict__ char_ids,     // (B, S, L)
    const int*    __restrict__ char_len,     // (B, S)
    const int*    __restrict__ action_ids,   // (B, S)
    const int*    __restrict__ slot_type,    // (B, S)
    const float4* __restrict__ char_table,   // (N_CHAR, 64)
    const float4* __restrict__ action_table, // (N_ACT, 64)
    float4*       __restrict__ out)          // (B, 5, 64)
{
    const int gtid = blockIdx.x * blockDim.x + threadIdx.x;
    const int b    = gtid >> 5;
    const int lane = gtid & 31;
    if (b >= BB) return;

    // Up-front, fully independent control loads (contiguous per b).
    const int4 st = __ldg((const int4*)(slot_type  + b * SS));
    const int4 cl = __ldg((const int4*)(char_len   + b * SS));
    const int4 ai = __ldg((const int4*)(action_ids + b * SS));

    float4* obase = out + (long long)b * 5 * D4;

    // BOS row (action_table row 98 is L1-hot).
    {
        const float4 r0 = __ldg(&action_table[BOS_ID * D4 + lane]);
        const float4 r1 = __ldg(&action_table[BOS_ID * D4 + 32 + lane]);
        obase[lane]      = r0;
        obase[lane + 32] = r1;
    }

    #pragma unroll
    for (int s = 0; s < SS; ++s) {
        const int t = comp(st, s);                    // warp-uniform
        float4 r0, r1;
        if (t == 0) {
            const int len = comp(cl, s);              // 1..15
            const int4* ids4 = (const int4*)(char_ids + (b * SS + s) * LL);
            float4 a0 = make_float4(0.f, 0.f, 0.f, 0.f);
            float4 a1 = make_float4(0.f, 0.f, 0.f, 0.f);
            const int nb = (len + 3) >> 2;            // 1..4
            for (int i = 0; i < nb; ++i) {
                const int4 id = __ldg(&ids4[i]);      // warp-uniform LDG.128
                const int base = i << 2;
                // 8 independent L1-hit gathers in flight.
                const float4 ex0 = __ldg(&char_table[id.x * D4 + lane]);
                const float4 ex1 = __ldg(&char_table[id.x * D4 + 32 + lane]);
                const float4 ey0 = __ldg(&char_table[id.y * D4 + lane]);
                const float4 ey1 = __ldg(&char_table[id.y * D4 + 32 + lane]);
                const float4 ez0 = __ldg(&char_table[id.z * D4 + lane]);
                const float4 ez1 = __ldg(&char_table[id.z * D4 + 32 + lane]);
                const float4 ew0 = __ldg(&char_table[id.w * D4 + lane]);
                const float4 ew1 = __ldg(&char_table[id.w * D4 + 32 + lane]);
                // Branchless len-masking (ids past len are valid indices, weight 0).
                const float my = (base + 1 < len) ? 1.0f : 0.0f;
                const float mz = (base + 2 < len) ? 1.0f : 0.0f;
                const float mw = (base + 3 < len) ? 1.0f : 0.0f;
                a0.x += ex0.x; a0.y += ex0.y; a0.z += ex0.z; a0.w += ex0.w;
                a1.x += ex1.x; a1.y += ex1.y; a1.z += ex1.z; a1.w += ex1.w;
                a0.x = fmaf(my, ey0.x, a0.x); a0.y = fmaf(my, ey0.y, a0.y);
                a0.z = fmaf(my, ey0.z, a0.z); a0.w = fmaf(my, ey0.w, a0.w);
                a1.x = fmaf(my, ey1.x, a1.x); a1.y = fmaf(my, ey1.y, a1.y);
                a1.z = fmaf(my, ey1.z, a1.z); a1.w = fmaf(my, ey1.w, a1.w);
                a0.x = fmaf(mz, ez0.x, a0.x); a0.y = fmaf(mz, ez0.y, a0.y);
                a0.z = fmaf(mz, ez0.z, a0.z); a0.w = fmaf(mz, ez0.w, a0.w);
                a1.x = fmaf(mz, ez1.x, a1.x); a1.y = fmaf(mz, ez1.y, a1.y);
                a1.z = fmaf(mz, ez1.z, a1.z); a1.w = fmaf(mz, ez1.w, a1.w);
                a0.x = fmaf(mw, ew0.x, a0.x); a0.y = fmaf(mw, ew0.y, a0.y);
                a0.z = fmaf(mw, ew0.z, a0.z); a0.w = fmaf(mw, ew0.w, a0.w);
                a1.x = fmaf(mw, ew1.x, a1.x); a1.y = fmaf(mw, ew1.y, a1.y);
                a1.z = fmaf(mw, ew1.z, a1.z); a1.w = fmaf(mw, ew1.w, a1.w);
            }
            const float inv = 1.0f / (float)len;
            r0.x = a0.x * inv; r0.y = a0.y * inv; r0.z = a0.z * inv; r0.w = a0.w * inv;
            r1.x = a1.x * inv; r1.y = a1.y * inv; r1.z = a1.z * inv; r1.w = a1.w * inv;
        } else if (t == 1) {
            const int a = comp(ai, s);
            r0 = __ldg(&action_table[a * D4 + lane]);
            r1 = __ldg(&action_table[a * D4 + 32 + lane]);
        } else {
            r0 = make_float4(0.f, 0.f, 0.f, 0.f);
            r1 = make_float4(0.f, 0.f, 0.f, 0.f);
        }
        float4* orow = obase + (s + 1) * D4;
        orow[lane]      = r0;
        orow[lane + 32] = r1;
    }
}

extern "C" void kernel_launch(void* const* d_in, const int* in_sizes, int n_in,
                              void* d_out, int out_size)
{
    const int*    char_ids     = (const int*)   d_in[0];
    const int*    char_len     = (const int*)   d_in[1];
    const int*    action_ids   = (const int*)   d_in[2];
    const int*    slot_type    = (const int*)   d_in[3];
    const float4* char_table   = (const float4*)d_in[4];
    const float4* action_table = (const float4*)d_in[5];
    float4*       out          = (float4*)      d_out;

    const int threads = 256;                       // 8 warps -> 8 batch elems per block
    const int blocks  = (BB * 32) / threads;       // 2048
    actions_emb_kernel<<<blocks, threads>>>(char_ids, char_len, action_ids,
                                            slot_type, char_table, action_table, out);
}

// round 5
// speedup vs baseline: 1.0569x; 1.0569x over previous
#include <cuda_runtime.h>
#include <cuda_bf16.h>

#define BB 16384
#define SS 4
#define LL 16
#define DD 256
#define BOS_ID 98
#define D4 (DD / 4)          // 64 float4 per row
#define NROWS (BB * SS)      // 65536 slot rows

#define SLOTB 1024           // blocks doing slot rows
#define BOSB  160            // blocks doing BOS broadcast rows
#define WPB   8              // warps per block (256 threads)

struct Ctl {
    int  st, len, ai;
    int4 i0, i1, i2, i3;
};

__device__ __forceinline__ Ctl load_ctl(
    const int* __restrict__ char_ids, const int* __restrict__ char_len,
    const int* __restrict__ action_ids, const int* __restrict__ slot_type, int r)
{
    Ctl c;
    // All 7 loads independent -> single DRAM round-trip of latency.
    c.st  = __ldg(&slot_type[r]);
    c.len = __ldg(&char_len[r]);
    c.ai  = __ldg(&action_ids[r]);
    const int4* p = (const int4*)(char_ids + r * LL);
    c.i0 = __ldg(&p[0]); c.i1 = __ldg(&p[1]);
    c.i2 = __ldg(&p[2]); c.i3 = __ldg(&p[3]);
    return c;
}

__device__ __forceinline__ void acc4(float4& a0, float4& a1, float m,
                                     const float4 e0, const float4 e1)
{
    a0.x = fmaf(m, e0.x, a0.x); a0.y = fmaf(m, e0.y, a0.y);
    a0.z = fmaf(m, e0.z, a0.z); a0.w = fmaf(m, e0.w, a0.w);
    a1.x = fmaf(m, e1.x, a1.x); a1.y = fmaf(m, e1.y, a1.y);
    a1.z = fmaf(m, e1.z, a1.z); a1.w = fmaf(m, e1.w, a1.w);
}

__device__ __forceinline__ void process_row(
    const Ctl& c, int r, int lane,
    const float4* __restrict__ char_table,
    const float4* __restrict__ action_table,
    float4* __restrict__ out)
{
    float4 r0, r1;
    if (c.st == 0) {
        const int len = c.len;                 // 1..15, warp-uniform
        float4 a0 = make_float4(0.f, 0.f, 0.f, 0.f);
        float4 a1 = make_float4(0.f, 0.f, 0.f, 0.f);
        const int ids[16] = { c.i0.x, c.i0.y, c.i0.z, c.i0.w,
                              c.i1.x, c.i1.y, c.i1.z, c.i1.w,
                              c.i2.x, c.i2.y, c.i2.z, c.i2.w,
                              c.i3.x, c.i3.y, c.i3.z, c.i3.w };
        const int nb = (len + 3) >> 2;         // 1..4 batches of 4 ids
        #pragma unroll 1
        for (int i = 0; i < nb; ++i) {
            const int base = i << 2;
            const int idx = ids[base + 0], idy = ids[base + 1];
            const int idz = ids[base + 2], idw = ids[base + 3];
            // 8 independent L1-hit gathers in flight.
            const float4 ex0 = __ldg(&char_table[idx * D4 + lane]);
            const float4 ex1 = __ldg(&char_table[idx * D4 + 32 + lane]);
            const float4 ey0 = __ldg(&char_table[idy * D4 + lane]);
            const float4 ey1 = __ldg(&char_table[idy * D4 + 32 + lane]);
            const float4 ez0 = __ldg(&char_table[idz * D4 + lane]);
            const float4 ez1 = __ldg(&char_table[idz * D4 + 32 + lane]);
            const float4 ew0 = __ldg(&char_table[idw * D4 + lane]);
            const float4 ew1 = __ldg(&char_table[idw * D4 + 32 + lane]);
            const float my = (base + 1 < len) ? 1.0f : 0.0f;
            const float mz = (base + 2 < len) ? 1.0f : 0.0f;
            const float mw = (base + 3 < len) ? 1.0f : 0.0f;
            acc4(a0, a1, 1.0f, ex0, ex1);
            acc4(a0, a1, my,   ey0, ey1);
            acc4(a0, a1, mz,   ez0, ez1);
            acc4(a0, a1, mw,   ew0, ew1);
        }
        const float inv = 1.0f / (float)len;
        r0.x = a0.x * inv; r0.y = a0.y * inv; r0.z = a0.z * inv; r0.w = a0.w * inv;
        r1.x = a1.x * inv; r1.y = a1.y * inv; r1.z = a1.z * inv; r1.w = a1.w * inv;
    } else if (c.st == 1) {
        r0 = __ldg(&action_table[c.ai * D4 + lane]);
        r1 = __ldg(&action_table[c.ai * D4 + 32 + lane]);
    } else {
        r0 = make_float4(0.f, 0.f, 0.f, 0.f);
        r1 = make_float4(0.f, 0.f, 0.f, 0.f);
    }
    // slot row r = b*SS+s maps to output row b*5 + s + 1
    const int orow = (r >> 2) * 5 + (r & 3) + 1;
    float4* o = out + (long long)orow * D4;
    o[lane]      = r0;
    o[lane + 32] = r1;
}

__global__ void __launch_bounds__(256) actions_emb_kernel(
    const int*    __restrict__ char_ids,
    const int*    __restrict__ char_len,
    const int*    __restrict__ action_ids,
    const int*    __restrict__ slot_type,
    const float4* __restrict__ char_table,
    const float4* __restrict__ action_table,
    float4*       __restrict__ out)
{
    const int warp = threadIdx.x >> 5;
    const int lane = threadIdx.x & 31;

    if (blockIdx.x >= SLOTB) {
        // ---- BOS broadcast: all 16384 rows identical, register-held ----
        const float4 r0 = __ldg(&action_table[BOS_ID * D4 + lane]);
        const float4 r1 = __ldg(&action_table[BOS_ID * D4 + 32 + lane]);
        const int w  = (blockIdx.x - SLOTB) * WPB + warp;     // 0..BOSB*8-1
        const int W  = BOSB * WPB;                            // 1280
        for (int b = w; b < BB; b += W) {
            float4* o = out + (long long)(b * 5) * D4;
            o[lane]      = r0;
            o[lane + 32] = r1;
        }
        return;
    }

    // ---- Slot rows: grid-stride with 1-stage control prefetch ----
    const int w = blockIdx.x * WPB + warp;    // 0..SLOTB*8-1
    const int W = SLOTB * WPB;                // 8192 warps, 8 rows each

    int r = w;
    if (r >= NROWS) return;
    Ctl cur = load_ctl(char_ids, char_len, action_ids, slot_type, r);

    for (; r < NROWS; r += W) {
        const int rn = r + W;
        Ctl nxt;
        if (rn < NROWS)
            nxt = load_ctl(char_ids, char_len, action_ids, slot_type, rn);
        process_row(cur, r, lane, char_table, action_table, out);
        cur = nxt;
    }
}

extern "C" void kernel_launch(void* const* d_in, const int* in_sizes, int n_in,
                              void* d_out, int out_size)
{
    const int*    char_ids     = (const int*)   d_in[0];
    const int*    char_len     = (const int*)   d_in[1];
    const int*    action_ids   = (const int*)   d_in[2];
    const int*    slot_type    = (const int*)   d_in[3];
    const float4* char_table   = (const float4*)d_in[4];
    const float4* action_table = (const float4*)d_in[5];
    float4*       out          = (float4*)      d_out;

    actions_emb_kernel<<<SLOTB + BOSB, 256>>>(char_ids, char_len, action_ids,
                                              slot_type, char_table, action_table, out);
}

// round 6
// speedup vs baseline: 1.1778x; 1.1144x over previous
#include <cuda_runtime.h>
#include <cuda_bf16.h>

#define BB 16384
#define SS 4
#define LL 16
#define DD 256
#define BOS_ID 98
#define D4 (DD / 4)   // 64 float4 per row

__device__ __forceinline__ void acc4(float4& a0, float4& a1, float m,
                                     const float4 e0, const float4 e1)
{
    a0.x = fmaf(m, e0.x, a0.x); a0.y = fmaf(m, e0.y, a0.y);
    a0.z = fmaf(m, e0.z, a0.z); a0.w = fmaf(m, e0.w, a0.w);
    a1.x = fmaf(m, e1.x, a1.x); a1.y = fmaf(m, e1.y, a1.y);
    a1.z = fmaf(m, e1.z, a1.z); a1.w = fmaf(m, e1.w, a1.w);
}

// One warp per output row of (B, 5, 256). Lane owns cols lane, lane+32.
// All control loads issued in parallel before any branch -> single DRAM
// round-trip on the critical path.
__global__ void __launch_bounds__(128) actions_emb_kernel(
    const int*    __restrict__ char_ids,     // (B, S, L)
    const int*    __restrict__ char_len,     // (B, S)
    const int*    __restrict__ action_ids,   // (B, S)
    const int*    __restrict__ slot_type,    // (B, S)
    const float4* __restrict__ char_table,   // (N_CHAR, 64)
    const float4* __restrict__ action_table, // (N_ACT, 64)
    float4*       __restrict__ out)          // (B, 5, 64)
{
    const int gtid = blockIdx.x * blockDim.x + threadIdx.x;
    const int row  = gtid >> 5;
    const int lane = gtid & 31;
    if (row >= BB * 5) return;

    const int s = row % 5;
    const int b = row / 5;

    float4 r0, r1;

    if (s == 0) {
        // BOS: action_table row 98, L1-hot.
        r0 = __ldg(&action_table[BOS_ID * D4 + lane]);
        r1 = __ldg(&action_table[BOS_ID * D4 + 32 + lane]);
    } else {
        const int bs = b * SS + (s - 1);
        // ---- 7 independent loads, one DRAM round-trip ----
        const int  st  = __ldg(&slot_type[bs]);
        const int  len = __ldg(&char_len[bs]);
        const int  ai  = __ldg(&action_ids[bs]);
        const int4* p  = (const int4*)(char_ids + bs * LL);
        const int4 i0  = __ldg(&p[0]);
        const int4 i1  = __ldg(&p[1]);
        const int4 i2  = __ldg(&p[2]);
        const int4 i3  = __ldg(&p[3]);

        if (st == 0) {
            const int ids[16] = { i0.x, i0.y, i0.z, i0.w,  i1.x, i1.y, i1.z, i1.w,
                                  i2.x, i2.y, i2.z, i2.w,  i3.x, i3.y, i3.z, i3.w };
            float4 a0 = make_float4(0.f, 0.f, 0.f, 0.f);
            float4 a1 = make_float4(0.f, 0.f, 0.f, 0.f);
            const int nb = (len + 3) >> 2;            // 1..4 batches
            #pragma unroll 1
            for (int i = 0; i < nb; ++i) {
                const int base = i << 2;
                const int idx = ids[base + 0], idy = ids[base + 1];
                const int idz = ids[base + 2], idw = ids[base + 3];
                // 8 independent L1-hit gathers in flight.
                const float4 ex0 = __ldg(&char_table[idx * D4 + lane]);
                const float4 ex1 = __ldg(&char_table[idx * D4 + 32 + lane]);
                const float4 ey0 = __ldg(&char_table[idy * D4 + lane]);
                const float4 ey1 = __ldg(&char_table[idy * D4 + 32 + lane]);
                const float4 ez0 = __ldg(&char_table[idz * D4 + lane]);
                const float4 ez1 = __ldg(&char_table[idz * D4 + 32 + lane]);
                const float4 ew0 = __ldg(&char_table[idw * D4 + lane]);
                const float4 ew1 = __ldg(&char_table[idw * D4 + 32 + lane]);
                const float my = (base + 1 < len) ? 1.0f : 0.0f;
                const float mz = (base + 2 < len) ? 1.0f : 0.0f;
                const float mw = (base + 3 < len) ? 1.0f : 0.0f;
                acc4(a0, a1, 1.0f, ex0, ex1);
                acc4(a0, a1, my,   ey0, ey1);
                acc4(a0, a1, mz,   ez0, ez1);
                acc4(a0, a1, mw,   ew0, ew1);
            }
            const float inv = 1.0f / (float)len;
            r0.x = a0.x * inv; r0.y = a0.y * inv; r0.z = a0.z * inv; r0.w = a0.w * inv;
            r1.x = a1.x * inv; r1.y = a1.y * inv; r1.z = a1.z * inv; r1.w = a1.w * inv;
        } else if (st == 1) {
            r0 = __ldg(&action_table[ai * D4 + lane]);
            r1 = __ldg(&action_table[ai * D4 + 32 + lane]);
        } else {
            r0 = make_float4(0.f, 0.f, 0.f, 0.f);
            r1 = make_float4(0.f, 0.f, 0.f, 0.f);
        }
    }

    float4* orow = out + (long long)row * D4;
    orow[lane]      = r0;
    orow[lane + 32] = r1;
}

extern "C" void kernel_launch(void* const* d_in, const int* in_sizes, int n_in,
                              void* d_out, int out_size)
{
    const int*    char_ids     = (const int*)   d_in[0];
    const int*    char_len     = (const int*)   d_in[1];
    const int*    action_ids   = (const int*)   d_in[2];
    const int*    slot_type    = (const int*)   d_in[3];
    const float4* char_table   = (const float4*)d_in[4];
    const float4* action_table = (const float4*)d_in[5];
    float4*       out          = (float4*)      d_out;

    const int rows    = BB * 5;                 // 81920 warps
    const int threads = 128;                    // 4 warps per block
    const int blocks  = (rows * 32) / threads;  // 20480
    actions_emb_kernel<<<blocks, threads>>>(char_ids, char_len, action_ids,
                                            slot_type, char_table, action_table, out);
}

// round 7
// speedup vs baseline: 1.2485x; 1.0600x over previous
#include <cuda_runtime.h>
#include <cuda_bf16.h>

#define BB 16384
#define SS 4
#define LL 16
#define DD 256
#define BOS_ID 98
#define D4 (DD / 4)          // 64 16B-vectors per row
#define NROWS (BB * SS)      // 65536 slot rows

#define SLOTB 16384          // slot blocks: 4 warps each, 1 warp = 1 slot row
#define BOSB  160            // BOS broadcast blocks

typedef unsigned long long u64;

// ---- packed f32x2 helpers (2 floats per instruction) ----
__device__ __forceinline__ void add2(u64& a, u64 e) {
    asm("add.rn.f32x2 %0, %0, %1;" : "+l"(a) : "l"(e));
}
__device__ __forceinline__ u64 dup2(float m) {
    u64 r; asm("mov.b64 %0, {%1, %1};" : "=l"(r) : "f"(m)); return r;
}
__device__ __forceinline__ void mul2(u64& a, u64 m) {
    asm("mul.rn.f32x2 %0, %0, %1;" : "+l"(a) : "l"(m));
}

__global__ void __launch_bounds__(128) actions_emb_kernel(
    const int*       __restrict__ char_ids,     // (B, S, L)
    const int*       __restrict__ char_len,     // (B, S)
    const int*       __restrict__ action_ids,   // (B, S)
    const int*       __restrict__ slot_type,    // (B, S)
    const ulonglong2* __restrict__ char_table,  // (N_CHAR, 64) as 16B vecs
    const ulonglong2* __restrict__ action_table,// (N_ACT, 64)
    ulonglong2*      __restrict__ out)          // (B, 5, 64)
{
    const int warp = threadIdx.x >> 5;
    const int lane = threadIdx.x & 31;

    if (blockIdx.x >= SLOTB) {
        // ---- BOS rows: all identical, register-held broadcast ----
        const ulonglong2 r0 = action_table[BOS_ID * D4 + lane];
        const ulonglong2 r1 = action_table[BOS_ID * D4 + 32 + lane];
        const int w = (blockIdx.x - SLOTB) * 4 + warp;   // 0..BOSB*4-1
        const int W = BOSB * 4;                          // 640 warps
        for (int b = w; b < BB; b += W) {
            ulonglong2* o = out + (long long)(b * 5) * D4;
            o[lane]      = r0;
            o[lane + 32] = r1;
        }
        return;
    }

    // ---- one warp per slot row ----
    const int r = blockIdx.x * 4 + warp;                 // 0..65535
    // 7 independent control loads -> one DRAM round-trip.
    const int  st  = __ldg(&slot_type[r]);
    const int  len = __ldg(&char_len[r]);                // 1..15
    const int  ai  = __ldg(&action_ids[r]);
    const int4* p  = (const int4*)(char_ids + r * LL);
    const int4 i0  = __ldg(&p[0]);
    const int4 i1  = __ldg(&p[1]);
    const int4 i2  = __ldg(&p[2]);
    const int4 i3  = __ldg(&p[3]);

    ulonglong2 r0, r1;

    if (st == 0) {
        u64 a0l = 0, a0h = 0, a1l = 0, a1h = 0;          // 4 packed accumulators

        // Full batches of 4 ids: 8 independent 16B loads, 8 packed adds, no masks.
        #define BATCH(idv)                                                      \
        {                                                                       \
            const ulonglong2 ex0 = char_table[(idv).x * D4 + lane];             \
            const ulonglong2 ex1 = char_table[(idv).x * D4 + 32 + lane];        \
            const ulonglong2 ey0 = char_table[(idv).y * D4 + lane];             \
            const ulonglong2 ey1 = char_table[(idv).y * D4 + 32 + lane];        \
            const ulonglong2 ez0 = char_table[(idv).z * D4 + lane];             \
            const ulonglong2 ez1 = char_table[(idv).z * D4 + 32 + lane];        \
            const ulonglong2 ew0 = char_table[(idv).w * D4 + lane];             \
            const ulonglong2 ew1 = char_table[(idv).w * D4 + 32 + lane];        \
            add2(a0l, ex0.x); add2(a0h, ex0.y); add2(a1l, ex1.x); add2(a1h, ex1.y); \
            add2(a0l, ey0.x); add2(a0h, ey0.y); add2(a1l, ey1.x); add2(a1h, ey1.y); \
            add2(a0l, ez0.x); add2(a0h, ez0.y); add2(a1l, ez1.x); add2(a1h, ez1.y); \
            add2(a0l, ew0.x); add2(a0h, ew0.y); add2(a1l, ew1.x); add2(a1h, ew1.y); \
        }

        const int nf  = len >> 2;        // 0..3 full batches
        const int rem = len & 3;         // 0..3 tail ids
        if (nf > 0) BATCH(i0);
        if (nf > 1) BATCH(i1);
        if (nf > 2) BATCH(i2);
        #undef BATCH

        if (rem) {
            // Tail int4 selected by uniform branches (no local array).
            int4 t = i0;
            if (nf == 1) t = i1;
            else if (nf == 2) t = i2;
            else if (nf == 3) t = i3;
            // Guarded independent loads, then adds.
            const ulonglong2 tx0 = char_table[t.x * D4 + lane];
            const ulonglong2 tx1 = char_table[t.x * D4 + 32 + lane];
            if (rem > 1) {
                const ulonglong2 ty0 = char_table[t.y * D4 + lane];
                const ulonglong2 ty1 = char_table[t.y * D4 + 32 + lane];
                if (rem > 2) {
                    const ulonglong2 tz0 = char_table[t.z * D4 + lane];
                    const ulonglong2 tz1 = char_table[t.z * D4 + 32 + lane];
                    add2(a0l, tz0.x); add2(a0h, tz0.y); add2(a1l, tz1.x); add2(a1h, tz1.y);
                }
                add2(a0l, ty0.x); add2(a0h, ty0.y); add2(a1l, ty1.x); add2(a1h, ty1.y);
            }
            add2(a0l, tx0.x); add2(a0h, tx0.y); add2(a1l, tx1.x); add2(a1h, tx1.y);
        }

        const u64 inv = dup2(1.0f / (float)len);
        mul2(a0l, inv); mul2(a0h, inv); mul2(a1l, inv); mul2(a1h, inv);
        r0.x = a0l; r0.y = a0h;
        r1.x = a1l; r1.y = a1h;
    } else if (st == 1) {
        r0 = action_table[ai * D4 + lane];
        r1 = action_table[ai * D4 + 32 + lane];
    } else {
        r0.x = 0; r0.y = 0;
        r1.x = 0; r1.y = 0;
    }

    // slot row r = b*SS+s  ->  output row b*5 + s + 1
    const int orow = (r >> 2) * 5 + (r & 3) + 1;
    ulonglong2* o = out + (long long)orow * D4;
    o[lane]      = r0;
    o[lane + 32] = r1;
}

extern "C" void kernel_launch(void* const* d_in, const int* in_sizes, int n_in,
                              void* d_out, int out_size)
{
    const int* char_ids   = (const int*)d_in[0];
    const int* char_len   = (const int*)d_in[1];
    const int* action_ids = (const int*)d_in[2];
    const int* slot_type  = (const int*)d_in[3];
    const ulonglong2* char_table   = (const ulonglong2*)d_in[4];
    const ulonglong2* action_table = (const ulonglong2*)d_in[5];
    ulonglong2* out = (ulonglong2*)d_out;

    actions_emb_kernel<<<SLOTB + BOSB, 128>>>(char_ids, char_len, action_ids,
                                              slot_type, char_table, action_table, out);
}